// round 1
// baseline (speedup 1.0000x reference)
#include <cuda_runtime.h>
#include <cuda_bf16.h>
#include <math.h>

// ---------------- problem constants ----------------
#define BB   2
#define NN   10000
#define NT   20000           // BB*NN nodes
#define EE   160000          // edges per graph
#define EB   320000          // BB*EE batched edges
#define ET   340000          // EB + NT self loops
#define FIN  256
#define HID  256
#define HH   2
#define F1   512             // HH*HID
#define FOUT 256
#define NEG_SLOPE 0.2f

// ---------------- device scratch ----------------
__device__ float g_xw1[(size_t)NT * F1];     // x @ W1
__device__ float g_h  [(size_t)NT * F1];     // layer-1 output (post gelu)
__device__ float g_xw2[(size_t)NT * FOUT];   // h @ W2
__device__ float g_as1[NT * HH];
__device__ float g_ad1[NT * HH];
__device__ float g_as2[NT];
__device__ float g_ad2[NT];
__device__ int   g_cnt[NT + 1];
__device__ int   g_off[NT + 1];
__device__ int   g_srcidx[ET];

// ---------------- edge enumeration ----------------
__device__ __forceinline__ void edge_sd(int j, const int* ei, int& s, int& d) {
    if (j < EB) {
        int b = j / EE;
        int k = j - b * EE;
        s = ei[k]      + b * NN;
        d = ei[EE + k] + b * NN;
    } else {
        s = d = j - EB;
    }
}

// ---------------- SGEMM: C[M,N] = A[M,K] @ B[K,N], fp32 ----------------
// BM=128 BN=128 BK=16, 256 threads, 8x8 microtile. N,K multiples of (128,16); M guarded.
#define SG_BM 128
#define SG_BN 128
#define SG_BK 16
__global__ __launch_bounds__(256, 2)
void sgemm_kernel(const float* __restrict__ A, const float* __restrict__ Bm,
                  float* __restrict__ C, int M, int N, int K) {
    __shared__ float As[SG_BK][SG_BM + 4];
    __shared__ float Bs[SG_BK][SG_BN];

    int tid = threadIdx.x;
    int tx = tid & 15;         // 0..15 -> N
    int ty = tid >> 4;         // 0..15 -> M
    int bx = blockIdx.x;       // N tile
    int by = blockIdx.y;       // M tile

    int rowC = by * SG_BM + ty * 8;
    int colC = bx * SG_BN + tx * 8;

    float acc[8][8];
#pragma unroll
    for (int i = 0; i < 8; i++)
#pragma unroll
        for (int j = 0; j < 8; j++) acc[i][j] = 0.f;

    for (int k0 = 0; k0 < K; k0 += SG_BK) {
        // load A tile: 128x16 = 512 float4, 2 per thread
#pragma unroll
        for (int i = 0; i < 2; i++) {
            int idx = tid + i * 256;
            int r  = idx >> 2;
            int c4 = (idx & 3) << 2;
            int gr = by * SG_BM + r;
            float4 v = make_float4(0.f, 0.f, 0.f, 0.f);
            if (gr < M) v = *(const float4*)(A + (size_t)gr * K + k0 + c4);
            As[c4 + 0][r] = v.x;
            As[c4 + 1][r] = v.y;
            As[c4 + 2][r] = v.z;
            As[c4 + 3][r] = v.w;
            // B tile: 16x128 = 512 float4
            int rB  = idx >> 5;
            int cB4 = (idx & 31) << 2;
            float4 w = *(const float4*)(Bm + (size_t)(k0 + rB) * N + bx * SG_BN + cB4);
            *(float4*)&Bs[rB][cB4] = w;
        }
        __syncthreads();

#pragma unroll
        for (int kk = 0; kk < SG_BK; kk++) {
            float a[8], b[8];
            *(float4*)&a[0] = *(const float4*)&As[kk][ty * 8];
            *(float4*)&a[4] = *(const float4*)&As[kk][ty * 8 + 4];
            *(float4*)&b[0] = *(const float4*)&Bs[kk][tx * 8];
            *(float4*)&b[4] = *(const float4*)&Bs[kk][tx * 8 + 4];
#pragma unroll
            for (int i = 0; i < 8; i++)
#pragma unroll
                for (int j = 0; j < 8; j++) acc[i][j] += a[i] * b[j];
        }
        __syncthreads();
    }

#pragma unroll
    for (int i = 0; i < 8; i++) {
        int gr = rowC + i;
        if (gr < M) {
            *(float4*)(C + (size_t)gr * N + colC)     = *(float4*)&acc[i][0];
            *(float4*)(C + (size_t)gr * N + colC + 4) = *(float4*)&acc[i][4];
        }
    }
}

// ---------------- alpha (layer 1): warp per node, 2 heads ----------------
__global__ void alpha1_kernel(const float* __restrict__ att_src,
                              const float* __restrict__ att_dst) {
    int gid = blockIdx.x * blockDim.x + threadIdx.x;
    if (gid < NT + 1) g_cnt[gid] = 0;     // fused: zero CSR counters
    int w = gid >> 5;
    int lane = gid & 31;
    if (w >= NT) return;
    const float* xw = g_xw1 + (size_t)w * F1;
#pragma unroll
    for (int h = 0; h < HH; h++) {
        float ps = 0.f, pd = 0.f;
#pragma unroll
        for (int it = 0; it < 8; it++) {
            int c = lane + it * 32;
            float v = xw[h * HID + c];
            ps += v * att_src[h * HID + c];
            pd += v * att_dst[h * HID + c];
        }
#pragma unroll
        for (int o = 16; o > 0; o >>= 1) {
            ps += __shfl_xor_sync(0xffffffffu, ps, o);
            pd += __shfl_xor_sync(0xffffffffu, pd, o);
        }
        if (lane == 0) { g_as1[w * HH + h] = ps; g_ad1[w * HH + h] = pd; }
    }
}

// ---------------- alpha (layer 2): warp per node, 1 head ----------------
__global__ void alpha2_kernel(const float* __restrict__ att_src,
                              const float* __restrict__ att_dst) {
    int gid = blockIdx.x * blockDim.x + threadIdx.x;
    int w = gid >> 5;
    int lane = gid & 31;
    if (w >= NT) return;
    const float* xw = g_xw2 + (size_t)w * FOUT;
    float ps = 0.f, pd = 0.f;
#pragma unroll
    for (int it = 0; it < 8; it++) {
        int c = lane + it * 32;
        float v = xw[c];
        ps += v * att_src[c];
        pd += v * att_dst[c];
    }
#pragma unroll
    for (int o = 16; o > 0; o >>= 1) {
        ps += __shfl_xor_sync(0xffffffffu, ps, o);
        pd += __shfl_xor_sync(0xffffffffu, pd, o);
    }
    if (lane == 0) { g_as2[w] = ps; g_ad2[w] = pd; }
}

// ---------------- CSR build ----------------
__global__ void count_kernel(const int* __restrict__ ei) {
    int j = blockIdx.x * blockDim.x + threadIdx.x;
    if (j >= ET) return;
    int s, d;
    edge_sd(j, ei, s, d);
    atomicAdd(&g_cnt[d], 1);
}

__global__ void scan_kernel() {
    __shared__ int sh[1024];
    int t = threadIdx.x;
    const int CH = 20;                      // 1024*20 >= NT
    int base = t * CH;
    int local[CH];
    int sum = 0;
#pragma unroll
    for (int i = 0; i < CH; i++) {
        int idx = base + i;
        int v = (idx < NT) ? g_cnt[idx] : 0;
        local[i] = v;
        sum += v;
    }
    sh[t] = sum;
    __syncthreads();
    for (int off = 1; off < 1024; off <<= 1) {
        int v = (t >= off) ? sh[t - off] : 0;
        __syncthreads();
        sh[t] += v;
        __syncthreads();
    }
    int run = sh[t] - sum;                  // exclusive prefix
#pragma unroll
    for (int i = 0; i < CH; i++) {
        int idx = base + i;
        if (idx < NT) { g_off[idx] = run; run += local[i]; }
    }
    if (t == 0) g_off[NT] = ET;
    // re-zero counters for use as fill cursors (all reads of g_cnt done pre-scan-sync)
    for (int i = t; i < NT + 1; i += 1024) g_cnt[i] = 0;
}

__global__ void fill_kernel(const int* __restrict__ ei) {
    int j = blockIdx.x * blockDim.x + threadIdx.x;
    if (j >= ET) return;
    int s, d;
    edge_sd(j, ei, s, d);
    int pos = atomicAdd(&g_cnt[d], 1);
    g_srcidx[g_off[d] + pos] = s;
}

// ---------------- layer-1 aggregation: warp per (dst, head), fused bias+GELU ----------------
__global__ void agg1_kernel(const float* __restrict__ b1) {
    int w = (blockIdx.x * blockDim.x + threadIdx.x) >> 5;
    int lane = threadIdx.x & 31;
    if (w >= NT * HH) return;
    int d = w >> 1;
    int h = w & 1;
    int beg = g_off[d], end = g_off[d + 1];
    float adh = g_ad1[d * HH + h];

    // pass 1: max (lane-parallel over edges)
    float m = -1e30f;
    for (int j = beg + lane; j < end; j += 32) {
        int s = g_srcidx[j];
        float e = g_as1[s * HH + h] + adh;
        e = e > 0.f ? e : NEG_SLOPE * e;
        m = fmaxf(m, e);
    }
#pragma unroll
    for (int o = 16; o > 0; o >>= 1) m = fmaxf(m, __shfl_xor_sync(0xffffffffu, m, o));

    // pass 2: exp-weighted vector accumulate
    float acc[8] = {0.f, 0.f, 0.f, 0.f, 0.f, 0.f, 0.f, 0.f};
    float denom = 0.f;
    for (int j = beg; j < end; j++) {
        int s = g_srcidx[j];
        float e = g_as1[s * HH + h] + adh;
        e = e > 0.f ? e : NEG_SLOPE * e;
        float ex = expf(e - m);
        denom += ex;
        const float* xs = g_xw1 + (size_t)s * F1 + h * HID;
#pragma unroll
        for (int k = 0; k < 8; k++) acc[k] += ex * xs[lane + k * 32];
    }
    float inv = 1.f / (denom + 1e-16f);
    float* outp = g_h + (size_t)d * F1 + h * HID;
#pragma unroll
    for (int k = 0; k < 8; k++) {
        int c = lane + k * 32;
        float v = acc[k] * inv + b1[h * HID + c];
        v = 0.5f * v * (1.f + erff(v * 0.70710678118654752f));   // exact gelu
        outp[c] = v;
    }
}

// ---------------- layer-2 aggregation: warp per dst, fused bias, writes d_out ----------------
__global__ void agg2_kernel(const float* __restrict__ b2, float* __restrict__ out) {
    int d = (blockIdx.x * blockDim.x + threadIdx.x) >> 5;
    int lane = threadIdx.x & 31;
    if (d >= NT) return;
    int beg = g_off[d], end = g_off[d + 1];
    float adh = g_ad2[d];

    float m = -1e30f;
    for (int j = beg + lane; j < end; j += 32) {
        int s = g_srcidx[j];
        float e = g_as2[s] + adh;
        e = e > 0.f ? e : NEG_SLOPE * e;
        m = fmaxf(m, e);
    }
#pragma unroll
    for (int o = 16; o > 0; o >>= 1) m = fmaxf(m, __shfl_xor_sync(0xffffffffu, m, o));

    float acc[8] = {0.f, 0.f, 0.f, 0.f, 0.f, 0.f, 0.f, 0.f};
    float denom = 0.f;
    for (int j = beg; j < end; j++) {
        int s = g_srcidx[j];
        float e = g_as2[s] + adh;
        e = e > 0.f ? e : NEG_SLOPE * e;
        float ex = expf(e - m);
        denom += ex;
        const float* xs = g_xw2 + (size_t)s * FOUT;
#pragma unroll
        for (int k = 0; k < 8; k++) acc[k] += ex * xs[lane + k * 32];
    }
    float inv = 1.f / (denom + 1e-16f);
    float* outp = out + (size_t)d * FOUT;
#pragma unroll
    for (int k = 0; k < 8; k++) {
        int c = lane + k * 32;
        outp[c] = acc[k] * inv + b2[c];
    }
}

// ---------------- launch ----------------
extern "C" void kernel_launch(void* const* d_in, const int* in_sizes, int n_in,
                              void* d_out, int out_size) {
    const float* x        = (const float*)d_in[0];
    const int*   ei       = (const int*)  d_in[1];
    const float* W1       = (const float*)d_in[2];
    const float* att_src1 = (const float*)d_in[3];
    const float* att_dst1 = (const float*)d_in[4];
    const float* b1       = (const float*)d_in[5];
    const float* W2       = (const float*)d_in[6];
    const float* att_src2 = (const float*)d_in[7];
    const float* att_dst2 = (const float*)d_in[8];
    const float* b2       = (const float*)d_in[9];
    float* out = (float*)d_out;

    float *p_xw1, *p_h, *p_xw2;
    cudaGetSymbolAddress((void**)&p_xw1, g_xw1);
    cudaGetSymbolAddress((void**)&p_h,   g_h);
    cudaGetSymbolAddress((void**)&p_xw2, g_xw2);

    // layer 1 GEMM: xw1 = x @ W1   [20000,256]@[256,512]
    {
        dim3 grid(F1 / SG_BN, (NT + SG_BM - 1) / SG_BM);
        sgemm_kernel<<<grid, 256>>>(x, W1, p_xw1, NT, F1, FIN);
    }
    // alpha1 (+ zero CSR counters)
    alpha1_kernel<<<(NT * 32 + 255) / 256, 256>>>(att_src1, att_dst1);
    // CSR build
    count_kernel<<<(ET + 255) / 256, 256>>>(ei);
    scan_kernel<<<1, 1024>>>();
    fill_kernel<<<(ET + 255) / 256, 256>>>(ei);
    // layer-1 aggregation + bias + gelu -> g_h
    agg1_kernel<<<(NT * HH * 32 + 255) / 256, 256>>>(b1);
    // layer 2 GEMM: xw2 = h @ W2   [20000,512]@[512,256]
    {
        dim3 grid(FOUT / SG_BN, (NT + SG_BM - 1) / SG_BM);
        sgemm_kernel<<<grid, 256>>>(p_h, W2, p_xw2, NT, FOUT, F1);
    }
    // alpha2
    alpha2_kernel<<<(NT * 32 + 255) / 256, 256>>>(att_src2, att_dst2);
    // layer-2 aggregation + bias -> output
    agg2_kernel<<<(NT * 32 + 255) / 256, 256>>>(b2, out);
}

// round 3
// speedup vs baseline: 1.5100x; 1.5100x over previous
#include <cuda_runtime.h>
#include <cuda_bf16.h>
#include <math.h>
#include <stdint.h>

// ---------------- problem constants ----------------
#define BB   2
#define NN   10000
#define NT   20000           // BB*NN nodes
#define EE   160000          // edges per graph
#define EB   320000          // BB*EE batched edges
#define ET   340000          // EB + NT self loops
#define FIN  256
#define HID  256
#define HH   2
#define F1   512             // HH*HID
#define FOUT 256
#define NEG_SLOPE 0.2f

// ---------------- device scratch ----------------
__device__ float g_xw1[(size_t)NT * F1];             // x @ W1 (fp32)
__device__ float g_xw2[(size_t)NT * FOUT];           // h @ W2 (fp32)
__device__ __nv_bfloat16 g_A1[(size_t)NT * 512];     // [x_hi(256) | x_lo(256)]
__device__ __nv_bfloat16 g_A2[(size_t)NT * 1024];    // [h_hi(512) | h_lo(512)]
__device__ __nv_bfloat16 g_Wt1[(size_t)512 * 512];   // W1^T: [n=512][hi(256)|lo(256)]
__device__ __nv_bfloat16 g_Wt2[(size_t)256 * 1024];  // W2^T: [n=256][hi(512)|lo(512)]
__device__ float g_as1[NT * HH];
__device__ float g_ad1[NT * HH];
__device__ float g_as2[NT];
__device__ float g_ad2[NT];
__device__ int   g_cnt[NT + 1];
__device__ int   g_off[NT + 1];
__device__ int   g_srcidx[ET];

// ---------------- helpers ----------------
__device__ __forceinline__ uint32_t smem_u32(const void* p) {
    return (uint32_t)__cvta_generic_to_shared(p);
}
__device__ __forceinline__ void cp16(uint32_t dst, const void* src, int src_sz) {
    asm volatile("cp.async.cg.shared.global [%0], [%1], 16, %2;"
                 :: "r"(dst), "l"(src), "r"(src_sz) : "memory");
}
__device__ __forceinline__ void cp_commit() {
    asm volatile("cp.async.commit_group;" ::: "memory");
}
template <int N>
__device__ __forceinline__ void cp_wait() {
    asm volatile("cp.async.wait_group %0;" :: "n"(N) : "memory");
}
__device__ __forceinline__ void ldm4(uint32_t* r, uint32_t addr) {
    asm volatile("ldmatrix.sync.aligned.m8n8.x4.shared.b16 {%0,%1,%2,%3}, [%4];"
                 : "=r"(r[0]), "=r"(r[1]), "=r"(r[2]), "=r"(r[3]) : "r"(addr));
}
__device__ __forceinline__ void mma16816(float* c, const uint32_t* a, const uint32_t* b) {
    asm volatile(
        "mma.sync.aligned.m16n8k16.row.col.f32.bf16.bf16.f32 "
        "{%0,%1,%2,%3}, {%4,%5,%6,%7}, {%8,%9}, {%0,%1,%2,%3};"
        : "+f"(c[0]), "+f"(c[1]), "+f"(c[2]), "+f"(c[3])
        : "r"(a[0]), "r"(a[1]), "r"(a[2]), "r"(a[3]), "r"(b[0]), "r"(b[1]));
}
__device__ __forceinline__ void split_bf16(float f, __nv_bfloat16& hi, __nv_bfloat16& lo) {
    hi = __float2bfloat16(f);
    lo = __float2bfloat16(f - __bfloat162float(hi));
}

// ---------------- bf16x3 mma.sync GEMM ----------------
// C[M,N] = A @ B^T with A:[M][2K] = [Ah|Al], Bt:[N][2K] = [Bh|Bl] (bf16),
// computing AhBh + AhBl + AlBh with fp32 accumulation. K = real reduction dim.
#define BM 128
#define BN 128
#define BKr 32                       // real-k per main-loop iter
#define TROW 80                      // bytes per smem tile row (32 bf16 + 16B pad)
#define TILE_B (128 * TROW)          // 10240 bytes per tile
#define STAGE_B (4 * TILE_B)         // Ah, Al, Bh, Bl
#define GEMM_SMEM (2 * STAGE_B)      // 81920 bytes (double buffered)

__global__ __launch_bounds__(256, 2)
void gemm_kernel(const __nv_bfloat16* __restrict__ A,
                 const __nv_bfloat16* __restrict__ Bt,
                 float* __restrict__ C, int M, int N, int K) {
    extern __shared__ char sm[];
    const int tid = threadIdx.x;
    const int lane = tid & 31;
    const int wid = tid >> 5;
    const int wm = wid & 3;          // 4 warps over M (32 rows each)
    const int wn = wid >> 2;         // 2 warps over N (64 cols each)
    const int m0 = blockIdx.y * BM;
    const int n0 = blockIdx.x * BN;
    const int K2 = 2 * K;
    const uint32_t sbase = smem_u32(sm);

    float acc[2][8][4];
#pragma unroll
    for (int i = 0; i < 2; i++)
#pragma unroll
        for (int j = 0; j < 8; j++)
#pragma unroll
            for (int t = 0; t < 4; t++) acc[i][j][t] = 0.f;

    // loader: thread -> (row = tid>>1, chunk pair = (tid&1)*2)
    const int lrow = tid >> 1;
    const int lcb = (tid & 1) * 32;          // byte offset within 64B row
    const uint32_t so = (uint32_t)(lrow * TROW + lcb);
    const __nv_bfloat16* gA = A + (size_t)(m0 + lrow) * K2 + (tid & 1) * 16;
    const __nv_bfloat16* gB = Bt + (size_t)(n0 + lrow) * K2 + (tid & 1) * 16;
    const int a_ok = (m0 + lrow) < M ? 16 : 0;

    const int NIT = K / BKr;

    // issue loads for iteration `it` into stage s
    auto issue = [&](int it, int s) {
        const int k0 = it * BKr;
        uint32_t d = sbase + s * STAGE_B + so;
        cp16(d,                   gA + k0,          a_ok);
        cp16(d + 16,              gA + k0 + 8,      a_ok);
        cp16(d + TILE_B,          gA + K + k0,      a_ok);
        cp16(d + TILE_B + 16,     gA + K + k0 + 8,  a_ok);
        cp16(d + 2 * TILE_B,      gB + k0,          16);
        cp16(d + 2 * TILE_B + 16, gB + k0 + 8,      16);
        cp16(d + 3 * TILE_B,      gB + K + k0,      16);
        cp16(d + 3 * TILE_B + 16, gB + K + k0 + 8,  16);
        cp_commit();
    };

    issue(0, 0);

    // fragment smem addressing (constant per thread)
    const uint32_t aOff = (uint32_t)((wm * 32 + (lane & 15)) * TROW + ((lane >> 4) * 16));
    const uint32_t bOff = (uint32_t)((wn * 64 + (lane & 7) + ((lane >> 4) << 3)) * TROW
                                     + (((lane >> 3) & 1) * 16));

    for (int it = 0; it < NIT; it++) {
        const int s = it & 1;
        if (it + 1 < NIT) {
            issue(it + 1, s ^ 1);
            cp_wait<1>();
        } else {
            cp_wait<0>();
        }
        __syncthreads();

        const uint32_t base = sbase + s * STAGE_B;
        const uint32_t aAddr = base + aOff;
        const uint32_t bAddr = base + 2 * TILE_B + bOff;
#pragma unroll
        for (int k16 = 0; k16 < 2; k16++) {
            uint32_t ah[2][4], al[2][4];
#pragma unroll
            for (int mf = 0; mf < 2; mf++) {
                ldm4(ah[mf], aAddr + mf * (16 * TROW) + k16 * 32);
                ldm4(al[mf], aAddr + TILE_B + mf * (16 * TROW) + k16 * 32);
            }
#pragma unroll
            for (int ng = 0; ng < 4; ng++) {
                uint32_t bh[4], bl[4];
                ldm4(bh, bAddr + ng * (16 * TROW) + k16 * 32);
                ldm4(bl, bAddr + TILE_B + ng * (16 * TROW) + k16 * 32);
#pragma unroll
                for (int mf = 0; mf < 2; mf++) {
#pragma unroll
                    for (int t = 0; t < 2; t++) {
                        float* c = acc[mf][ng * 2 + t];
                        mma16816(c, ah[mf], bh + 2 * t);
                        mma16816(c, ah[mf], bl + 2 * t);
                        mma16816(c, al[mf], bh + 2 * t);
                    }
                }
            }
        }
        __syncthreads();
    }

    // epilogue
#pragma unroll
    for (int mf = 0; mf < 2; mf++) {
        const int mA = m0 + wm * 32 + mf * 16 + (lane >> 2);
        const int mB = mA + 8;
#pragma unroll
        for (int nf = 0; nf < 8; nf++) {
            const int n = n0 + wn * 64 + nf * 8 + (lane & 3) * 2;
            const float* c = acc[mf][nf];
            if (mA < M) *(float2*)(C + (size_t)mA * N + n) = make_float2(c[0], c[1]);
            if (mB < M) *(float2*)(C + (size_t)mB * N + n) = make_float2(c[2], c[3]);
        }
    }
}

// ---------------- conversion kernels ----------------
__global__ void conv_x_kernel(const float* __restrict__ x) {
    int i = blockIdx.x * blockDim.x + threadIdx.x;
    if (i >= NT * 128) return;
    int row = i >> 7;
    int c2 = (i & 127) << 1;
    float2 f = *(const float2*)(x + (size_t)row * FIN + c2);
    __nv_bfloat16 h0, l0, h1, l1;
    split_bf16(f.x, h0, l0);
    split_bf16(f.y, h1, l1);
    __nv_bfloat162 hp; hp.x = h0; hp.y = h1;
    __nv_bfloat162 lp; lp.x = l0; lp.y = l1;
    *(__nv_bfloat162*)(g_A1 + (size_t)row * 512 + c2) = hp;
    *(__nv_bfloat162*)(g_A1 + (size_t)row * 512 + 256 + c2) = lp;
}

__global__ void conv_w1_kernel(const float* __restrict__ W1) {
    int i = blockIdx.x * blockDim.x + threadIdx.x;   // over 512*512
    if (i >= 512 * 512) return;
    int n = i >> 9, k = i & 511;
    int ks = k & 255;
    float f = W1[(size_t)ks * F1 + n];
    __nv_bfloat16 hi, lo;
    split_bf16(f, hi, lo);
    g_Wt1[i] = (k < 256) ? hi : lo;
}

__global__ void conv_w2_kernel(const float* __restrict__ W2) {
    int i = blockIdx.x * blockDim.x + threadIdx.x;   // over 256*1024
    if (i >= 256 * 1024) return;
    int n = i >> 10, k = i & 1023;
    int ks = k & 511;
    float f = W2[(size_t)ks * FOUT + n];
    __nv_bfloat16 hi, lo;
    split_bf16(f, hi, lo);
    g_Wt2[i] = (k < 512) ? hi : lo;
}

// ---------------- edge enumeration ----------------
__device__ __forceinline__ void edge_sd(int j, const int* ei, int& s, int& d) {
    if (j < EB) {
        int b = j / EE;
        int k = j - b * EE;
        s = ei[k]      + b * NN;
        d = ei[EE + k] + b * NN;
    } else {
        s = d = j - EB;
    }
}

// ---------------- alpha (layer 1): warp per node, 2 heads ----------------
__global__ void alpha1_kernel(const float* __restrict__ att_src,
                              const float* __restrict__ att_dst) {
    int gid = blockIdx.x * blockDim.x + threadIdx.x;
    if (gid < NT + 1) g_cnt[gid] = 0;     // fused: zero CSR counters
    int w = gid >> 5;
    int lane = gid & 31;
    if (w >= NT) return;
    const float* xw = g_xw1 + (size_t)w * F1;
#pragma unroll
    for (int h = 0; h < HH; h++) {
        float ps = 0.f, pd = 0.f;
#pragma unroll
        for (int it = 0; it < 8; it++) {
            int c = lane + it * 32;
            float v = xw[h * HID + c];
            ps += v * att_src[h * HID + c];
            pd += v * att_dst[h * HID + c];
        }
#pragma unroll
        for (int o = 16; o > 0; o >>= 1) {
            ps += __shfl_xor_sync(0xffffffffu, ps, o);
            pd += __shfl_xor_sync(0xffffffffu, pd, o);
        }
        if (lane == 0) { g_as1[w * HH + h] = ps; g_ad1[w * HH + h] = pd; }
    }
}

__global__ void alpha2_kernel(const float* __restrict__ att_src,
                              const float* __restrict__ att_dst) {
    int gid = blockIdx.x * blockDim.x + threadIdx.x;
    int w = gid >> 5;
    int lane = gid & 31;
    if (w >= NT) return;
    const float* xw = g_xw2 + (size_t)w * FOUT;
    float ps = 0.f, pd = 0.f;
#pragma unroll
    for (int it = 0; it < 8; it++) {
        int c = lane + it * 32;
        float v = xw[c];
        ps += v * att_src[c];
        pd += v * att_dst[c];
    }
#pragma unroll
    for (int o = 16; o > 0; o >>= 1) {
        ps += __shfl_xor_sync(0xffffffffu, ps, o);
        pd += __shfl_xor_sync(0xffffffffu, pd, o);
    }
    if (lane == 0) { g_as2[w] = ps; g_ad2[w] = pd; }
}

// ---------------- CSR build ----------------
__global__ void count_kernel(const int* __restrict__ ei) {
    int j = blockIdx.x * blockDim.x + threadIdx.x;
    if (j >= ET) return;
    int s, d;
    edge_sd(j, ei, s, d);
    atomicAdd(&g_cnt[d], 1);
}

__global__ void scan_kernel() {
    __shared__ int warp_base[32];
    int t = threadIdx.x;                 // 1024 threads
    int lane = t & 31, w = t >> 5;
    const int CH = 20;                   // 1024*20 >= NT
    int base = t * CH;
    int local[CH];
    int sum = 0;
#pragma unroll
    for (int i = 0; i < CH; i++) {
        int idx = base + i;
        int v = (idx < NT) ? g_cnt[idx] : 0;
        local[i] = v;
        sum += v;
    }
    int inc = sum;
#pragma unroll
    for (int o = 1; o < 32; o <<= 1) {
        int v = __shfl_up_sync(0xffffffffu, inc, o);
        if (lane >= o) inc += v;
    }
    if (lane == 31) warp_base[w] = inc;
    __syncthreads();
    if (t < 32) {
        int v = warp_base[t];
        int wi = v;
#pragma unroll
        for (int o = 1; o < 32; o <<= 1) {
            int u = __shfl_up_sync(0xffffffffu, wi, o);
            if (t >= o) wi += u;
        }
        warp_base[t] = wi - v;           // exclusive warp base
    }
    __syncthreads();
    int run = warp_base[w] + inc - sum;  // exclusive thread prefix
#pragma unroll
    for (int i = 0; i < CH; i++) {
        int idx = base + i;
        if (idx < NT) { g_off[idx] = run; run += local[i]; }
    }
    if (t == 0) g_off[NT] = ET;
    for (int i = t; i < NT + 1; i += 1024) g_cnt[i] = 0;  // reset cursors
}

__global__ void fill_kernel(const int* __restrict__ ei) {
    int j = blockIdx.x * blockDim.x + threadIdx.x;
    if (j >= ET) return;
    int s, d;
    edge_sd(j, ei, s, d);
    int pos = atomicAdd(&g_cnt[d], 1);
    g_srcidx[g_off[d] + pos] = s;
}

// ---------------- layer-1 aggregation: warp per (dst, head); writes split-bf16 h ----------------
__global__ void agg1_kernel(const float* __restrict__ b1) {
    int w = (blockIdx.x * blockDim.x + threadIdx.x) >> 5;
    int lane = threadIdx.x & 31;
    if (w >= NT * HH) return;
    int d = w >> 1;
    int h = w & 1;
    int beg = g_off[d], end = g_off[d + 1];
    float adh = g_ad1[d * HH + h];

    float m = -1e30f;
    for (int j = beg + lane; j < end; j += 32) {
        int s = g_srcidx[j];
        float e = g_as1[s * HH + h] + adh;
        e = e > 0.f ? e : NEG_SLOPE * e;
        m = fmaxf(m, e);
    }
#pragma unroll
    for (int o = 16; o > 0; o >>= 1) m = fmaxf(m, __shfl_xor_sync(0xffffffffu, m, o));

    float acc[8] = {0.f, 0.f, 0.f, 0.f, 0.f, 0.f, 0.f, 0.f};
    float denom = 0.f;
    for (int j = beg; j < end; j++) {
        int s = g_srcidx[j];
        float e = g_as1[s * HH + h] + adh;
        e = e > 0.f ? e : NEG_SLOPE * e;
        float ex = expf(e - m);
        denom += ex;
        const float* xs = g_xw1 + (size_t)s * F1 + h * HID;
#pragma unroll
        for (int k = 0; k < 8; k++) acc[k] += ex * xs[lane + k * 32];
    }
    float inv = 1.f / (denom + 1e-16f);
    __nv_bfloat16* outp = g_A2 + (size_t)d * 1024 + h * HID;
#pragma unroll
    for (int k = 0; k < 8; k++) {
        int c = lane + k * 32;
        float v = acc[k] * inv + b1[h * HID + c];
        v = 0.5f * v * (1.f + erff(v * 0.70710678118654752f));   // exact gelu
        __nv_bfloat16 hi, lo;
        split_bf16(v, hi, lo);
        outp[c] = hi;            // hi half at cols [0,512)
        outp[512 + c] = lo;      // lo half at cols [512,1024)
    }
}

// ---------------- layer-2 aggregation: warp per dst, fused bias, writes d_out ----------------
__global__ void agg2_kernel(const float* __restrict__ b2, float* __restrict__ out) {
    int d = (blockIdx.x * blockDim.x + threadIdx.x) >> 5;
    int lane = threadIdx.x & 31;
    if (d >= NT) return;
    int beg = g_off[d], end = g_off[d + 1];
    float adh = g_ad2[d];

    float m = -1e30f;
    for (int j = beg + lane; j < end; j += 32) {
        int s = g_srcidx[j];
        float e = g_as2[s] + adh;
        e = e > 0.f ? e : NEG_SLOPE * e;
        m = fmaxf(m, e);
    }
#pragma unroll
    for (int o = 16; o > 0; o >>= 1) m = fmaxf(m, __shfl_xor_sync(0xffffffffu, m, o));

    float acc[8] = {0.f, 0.f, 0.f, 0.f, 0.f, 0.f, 0.f, 0.f};
    float denom = 0.f;
    for (int j = beg; j < end; j++) {
        int s = g_srcidx[j];
        float e = g_as2[s] + adh;
        e = e > 0.f ? e : NEG_SLOPE * e;
        float ex = expf(e - m);
        denom += ex;
        const float* xs = g_xw2 + (size_t)s * FOUT;
#pragma unroll
        for (int k = 0; k < 8; k++) acc[k] += ex * xs[lane + k * 32];
    }
    float inv = 1.f / (denom + 1e-16f);
    float* outp = out + (size_t)d * FOUT;
#pragma unroll
    for (int k = 0; k < 8; k++) {
        int c = lane + k * 32;
        outp[c] = acc[k] * inv + b2[c];
    }
}

// ---------------- launch ----------------
extern "C" void kernel_launch(void* const* d_in, const int* in_sizes, int n_in,
                              void* d_out, int out_size) {
    const float* x        = (const float*)d_in[0];
    const int*   ei       = (const int*)  d_in[1];
    const float* W1       = (const float*)d_in[2];
    const float* att_src1 = (const float*)d_in[3];
    const float* att_dst1 = (const float*)d_in[4];
    const float* b1       = (const float*)d_in[5];
    const float* W2       = (const float*)d_in[6];
    const float* att_src2 = (const float*)d_in[7];
    const float* att_dst2 = (const float*)d_in[8];
    const float* b2       = (const float*)d_in[9];
    float* out = (float*)d_out;

    float *p_xw1, *p_xw2;
    __nv_bfloat16 *p_A1, *p_A2, *p_Wt1, *p_Wt2;
    cudaGetSymbolAddress((void**)&p_xw1, g_xw1);
    cudaGetSymbolAddress((void**)&p_xw2, g_xw2);
    cudaGetSymbolAddress((void**)&p_A1,  g_A1);
    cudaGetSymbolAddress((void**)&p_A2,  g_A2);
    cudaGetSymbolAddress((void**)&p_Wt1, g_Wt1);
    cudaGetSymbolAddress((void**)&p_Wt2, g_Wt2);

    static bool attr_done = false;
    if (!attr_done) {
        cudaFuncSetAttribute(gemm_kernel, cudaFuncAttributeMaxDynamicSharedMemorySize, GEMM_SMEM);
        attr_done = true;
    }

    // input conversions
    conv_x_kernel<<<(NT * 128 + 255) / 256, 256>>>(x);
    conv_w1_kernel<<<(512 * 512 + 255) / 256, 256>>>(W1);
    conv_w2_kernel<<<(256 * 1024 + 255) / 256, 256>>>(W2);

    // layer-1 GEMM (HMMA bf16x3): xw1 = x @ W1  (M=20000, N=512, Kreal=256)
    {
        dim3 grid(F1 / BN, (NT + BM - 1) / BM);
        gemm_kernel<<<grid, 256, GEMM_SMEM>>>(p_A1, p_Wt1, p_xw1, NT, F1, 256);
    }
    alpha1_kernel<<<(NT * 32 + 255) / 256, 256>>>(att_src1, att_dst1);
    count_kernel<<<(ET + 255) / 256, 256>>>(ei);
    scan_kernel<<<1, 1024>>>();
    fill_kernel<<<(ET + 255) / 256, 256>>>(ei);
    agg1_kernel<<<(NT * HH * 32 + 255) / 256, 256>>>(b1);

    // layer-2 GEMM: xw2 = h @ W2  (M=20000, N=256, Kreal=512)
    {
        dim3 grid(FOUT / BN, (NT + BM - 1) / BM);
        gemm_kernel<<<grid, 256, GEMM_SMEM>>>(p_A2, p_Wt2, p_xw2, NT, FOUT, 512);
    }
    alpha2_kernel<<<(NT * 32 + 255) / 256, 256>>>(att_src2, att_dst2);
    agg2_kernel<<<(NT * 32 + 255) / 256, 256>>>(b2, out);
}

// round 4
// speedup vs baseline: 1.5486x; 1.0256x over previous
#include <cuda_runtime.h>
#include <cuda_bf16.h>
#include <math.h>
#include <stdint.h>

// ---------------- problem constants ----------------
#define BB   2
#define NN   10000
#define NT   20000           // BB*NN nodes
#define EE   160000          // edges per graph
#define EB   320000          // BB*EE batched edges
#define ET   340000          // EB + NT self loops
#define FIN  256
#define HID  256
#define HH   2
#define F1   512             // HH*HID
#define FOUT 256
#define NEG_SLOPE 0.2f

// ---------------- device scratch ----------------
__device__ float g_xw1[(size_t)NT * F1];             // x @ W1 (fp32)
__device__ float g_xw2[(size_t)NT * FOUT];           // h @ W2 (fp32)
__device__ __nv_bfloat16 g_A1[(size_t)NT * 512];     // [x_hi(256) | x_lo(256)]
__device__ __nv_bfloat16 g_A2[(size_t)NT * 1024];    // [h_hi(512) | h_lo(512)]
__device__ __nv_bfloat16 g_Wt1[(size_t)512 * 512];   // W1^T: [n=512][hi(256)|lo(256)]
__device__ __nv_bfloat16 g_Wt2[(size_t)256 * 1024];  // W2^T: [n=256][hi(512)|lo(512)]
__device__ float g_as1[NT * HH];
__device__ float g_ad1[NT * HH];
__device__ float g_as2[NT];
__device__ float g_ad2[NT];
__device__ int   g_cnt[NT + 1];
__device__ int   g_off[NT + 1];
__device__ int   g_srcidx[ET];

// ---------------- helpers ----------------
__device__ __forceinline__ uint32_t smem_u32(const void* p) {
    return (uint32_t)__cvta_generic_to_shared(p);
}
__device__ __forceinline__ void cp16(uint32_t dst, const void* src, int src_sz) {
    asm volatile("cp.async.cg.shared.global [%0], [%1], 16, %2;"
                 :: "r"(dst), "l"(src), "r"(src_sz) : "memory");
}
__device__ __forceinline__ void cp_commit() {
    asm volatile("cp.async.commit_group;" ::: "memory");
}
template <int N>
__device__ __forceinline__ void cp_wait() {
    asm volatile("cp.async.wait_group %0;" :: "n"(N) : "memory");
}
__device__ __forceinline__ void ldm4(uint32_t* r, uint32_t addr) {
    asm volatile("ldmatrix.sync.aligned.m8n8.x4.shared.b16 {%0,%1,%2,%3}, [%4];"
                 : "=r"(r[0]), "=r"(r[1]), "=r"(r[2]), "=r"(r[3]) : "r"(addr));
}
__device__ __forceinline__ void mma16816(float* c, const uint32_t* a, const uint32_t* b) {
    asm volatile(
        "mma.sync.aligned.m16n8k16.row.col.f32.bf16.bf16.f32 "
        "{%0,%1,%2,%3}, {%4,%5,%6,%7}, {%8,%9}, {%0,%1,%2,%3};"
        : "+f"(c[0]), "+f"(c[1]), "+f"(c[2]), "+f"(c[3])
        : "r"(a[0]), "r"(a[1]), "r"(a[2]), "r"(a[3]), "r"(b[0]), "r"(b[1]));
}
__device__ __forceinline__ void split_bf16(float f, __nv_bfloat16& hi, __nv_bfloat16& lo) {
    hi = __float2bfloat16(f);
    lo = __float2bfloat16(f - __bfloat162float(hi));
}

// ---------------- bf16x3 mma.sync GEMM, 4-stage cp.async ----------------
// C[M,N] = A @ B^T with A:[M][2K] = [Ah|Al], Bt:[N][2K] = [Bh|Bl] (bf16),
// computing AhBh + AhBl + AlBh, fp32 accumulation.
#define BM 128
#define BN 128
#define BKr 16                       // real-k per main-loop iter
#define TROW 48                      // bytes per smem tile row (16 bf16 + 16B pad)
#define TILE_B (128 * TROW)          // 6144 bytes
#define STAGE_B (4 * TILE_B)         // Ah, Al, Bh, Bl = 24576
#define NSTG 4
#define GEMM_SMEM (NSTG * STAGE_B)   // 98304 bytes

__global__ __launch_bounds__(256, 2)
void gemm_kernel(const __nv_bfloat16* __restrict__ A,
                 const __nv_bfloat16* __restrict__ Bt,
                 float* __restrict__ C, int M, int N, int K) {
    extern __shared__ char sm[];
    const int tid = threadIdx.x;
    const int lane = tid & 31;
    const int wid = tid >> 5;
    const int wm = wid & 3;          // 4 warps over M (32 rows each)
    const int wn = wid >> 2;         // 2 warps over N (64 cols each)
    const int m0 = blockIdx.y * BM;
    const int n0 = blockIdx.x * BN;
    const int K2 = 2 * K;
    const uint32_t sbase = smem_u32(sm);

    float acc[2][8][4];
#pragma unroll
    for (int i = 0; i < 2; i++)
#pragma unroll
        for (int j = 0; j < 8; j++)
#pragma unroll
            for (int t = 0; t < 4; t++) acc[i][j][t] = 0.f;

    // loader: thread -> row = tid>>1 (0..127), 16B half = tid&1
    const int lrow = tid >> 1;
    const uint32_t so = (uint32_t)(lrow * TROW + (tid & 1) * 16);
    const __nv_bfloat16* gA = A + (size_t)(m0 + lrow) * K2 + (tid & 1) * 8;
    const __nv_bfloat16* gB = Bt + (size_t)(n0 + lrow) * K2 + (tid & 1) * 8;
    const int a_ok = (m0 + lrow) < M ? 16 : 0;

    const int NIT = K / BKr;

    auto issue = [&](int it) {
        const int s = it & (NSTG - 1);
        const int k0 = it * BKr;
        uint32_t d = sbase + s * STAGE_B + so;
        cp16(d,              gA + k0,     a_ok);
        cp16(d + TILE_B,     gA + K + k0, a_ok);
        cp16(d + 2 * TILE_B, gB + k0,     16);
        cp16(d + 3 * TILE_B, gB + K + k0, 16);
        cp_commit();
    };

    issue(0); issue(1); issue(2);

    const uint32_t aOff = (uint32_t)((wm * 32 + (lane & 15)) * TROW + ((lane >> 4) * 16));
    const uint32_t bOff = (uint32_t)((wn * 64 + (lane & 7) + ((lane >> 4) << 3)) * TROW
                                     + (((lane >> 3) & 1) * 16));

    for (int it = 0; it < NIT; it++) {
        const int s = it & (NSTG - 1);
        cp_wait<NSTG - 2>();
        __syncthreads();

        const uint32_t base = sbase + s * STAGE_B;
        uint32_t ah[2][4], al[2][4];
#pragma unroll
        for (int mf = 0; mf < 2; mf++) {
            ldm4(ah[mf], base + aOff + mf * (16 * TROW));
            ldm4(al[mf], base + TILE_B + aOff + mf * (16 * TROW));
        }
#pragma unroll
        for (int ng = 0; ng < 4; ng++) {
            uint32_t bh[4], bl[4];
            ldm4(bh, base + 2 * TILE_B + bOff + ng * (16 * TROW));
            ldm4(bl, base + 3 * TILE_B + bOff + ng * (16 * TROW));
#pragma unroll
            for (int mf = 0; mf < 2; mf++) {
#pragma unroll
                for (int t = 0; t < 2; t++) {
                    float* c = acc[mf][ng * 2 + t];
                    mma16816(c, ah[mf], bh + 2 * t);
                    mma16816(c, ah[mf], bl + 2 * t);
                    mma16816(c, al[mf], bh + 2 * t);
                }
            }
        }
        // issue next stage AFTER this iter's barrier -> safe overwrite of stage s-1
        if (it + 3 < NIT) issue(it + 3); else cp_commit();
    }

    // epilogue
#pragma unroll
    for (int mf = 0; mf < 2; mf++) {
        const int mA = m0 + wm * 32 + mf * 16 + (lane >> 2);
        const int mB = mA + 8;
#pragma unroll
        for (int nf = 0; nf < 8; nf++) {
            const int n = n0 + wn * 64 + nf * 8 + (lane & 3) * 2;
            const float* c = acc[mf][nf];
            if (mA < M) *(float2*)(C + (size_t)mA * N + n) = make_float2(c[0], c[1]);
            if (mB < M) *(float2*)(C + (size_t)mB * N + n) = make_float2(c[2], c[3]);
        }
    }
}

// ---------------- conversion kernels ----------------
__global__ void conv_x_kernel(const float* __restrict__ x) {
    int i = blockIdx.x * blockDim.x + threadIdx.x;
    if (i >= NT * 128) return;
    int row = i >> 7;
    int c2 = (i & 127) << 1;
    float2 f = *(const float2*)(x + (size_t)row * FIN + c2);
    __nv_bfloat16 h0, l0, h1, l1;
    split_bf16(f.x, h0, l0);
    split_bf16(f.y, h1, l1);
    __nv_bfloat162 hp; hp.x = h0; hp.y = h1;
    __nv_bfloat162 lp; lp.x = l0; lp.y = l1;
    *(__nv_bfloat162*)(g_A1 + (size_t)row * 512 + c2) = hp;
    *(__nv_bfloat162*)(g_A1 + (size_t)row * 512 + 256 + c2) = lp;
}

__global__ void conv_w1_kernel(const float* __restrict__ W1) {
    int i = blockIdx.x * blockDim.x + threadIdx.x;   // over 512*512
    if (i >= 512 * 512) return;
    int n = i >> 9, k = i & 511;
    int ks = k & 255;
    float f = W1[(size_t)ks * F1 + n];
    __nv_bfloat16 hi, lo;
    split_bf16(f, hi, lo);
    g_Wt1[i] = (k < 256) ? hi : lo;
}

__global__ void conv_w2_kernel(const float* __restrict__ W2) {
    int i = blockIdx.x * blockDim.x + threadIdx.x;   // over 256*1024
    if (i >= 256 * 1024) return;
    int n = i >> 10, k = i & 1023;
    int ks = k & 511;
    float f = W2[(size_t)ks * FOUT + n];
    __nv_bfloat16 hi, lo;
    split_bf16(f, hi, lo);
    g_Wt2[i] = (k < 512) ? hi : lo;
}

// ---------------- edge enumeration ----------------
__device__ __forceinline__ void edge_sd(int j, const int* ei, int& s, int& d) {
    if (j < EB) {
        int b = j / EE;
        int k = j - b * EE;
        s = ei[k]      + b * NN;
        d = ei[EE + k] + b * NN;
    } else {
        s = d = j - EB;
    }
}

// ---------------- alphas ----------------
__global__ void alpha1_kernel(const float* __restrict__ att_src,
                              const float* __restrict__ att_dst) {
    int gid = blockIdx.x * blockDim.x + threadIdx.x;
    int w = gid >> 5;
    int lane = gid & 31;
    if (w >= NT) return;
    const float* xw = g_xw1 + (size_t)w * F1;
#pragma unroll
    for (int h = 0; h < HH; h++) {
        float ps = 0.f, pd = 0.f;
#pragma unroll
        for (int it = 0; it < 8; it++) {
            int c = lane + it * 32;
            float v = xw[h * HID + c];
            ps += v * att_src[h * HID + c];
            pd += v * att_dst[h * HID + c];
        }
#pragma unroll
        for (int o = 16; o > 0; o >>= 1) {
            ps += __shfl_xor_sync(0xffffffffu, ps, o);
            pd += __shfl_xor_sync(0xffffffffu, pd, o);
        }
        if (lane == 0) { g_as1[w * HH + h] = ps; g_ad1[w * HH + h] = pd; }
    }
}

__global__ void alpha2_kernel(const float* __restrict__ att_src,
                              const float* __restrict__ att_dst) {
    int gid = blockIdx.x * blockDim.x + threadIdx.x;
    int w = gid >> 5;
    int lane = gid & 31;
    if (w >= NT) return;
    const float* xw = g_xw2 + (size_t)w * FOUT;
    float ps = 0.f, pd = 0.f;
#pragma unroll
    for (int it = 0; it < 8; it++) {
        int c = lane + it * 32;
        float v = xw[c];
        ps += v * att_src[c];
        pd += v * att_dst[c];
    }
#pragma unroll
    for (int o = 16; o > 0; o >>= 1) {
        ps += __shfl_xor_sync(0xffffffffu, ps, o);
        pd += __shfl_xor_sync(0xffffffffu, pd, o);
    }
    if (lane == 0) { g_as2[w] = ps; g_ad2[w] = pd; }
}

// ---------------- CSR build (runs on forked stream) ----------------
__global__ void zero_cnt_kernel() {
    int i = blockIdx.x * blockDim.x + threadIdx.x;
    if (i <= NT) g_cnt[i] = 0;
}

__global__ void count_kernel(const int* __restrict__ ei) {
    int j = blockIdx.x * blockDim.x + threadIdx.x;
    if (j >= ET) return;
    int s, d;
    edge_sd(j, ei, s, d);
    atomicAdd(&g_cnt[d], 1);
}

__global__ void scan_kernel() {
    __shared__ int warp_base[32];
    int t = threadIdx.x;                 // 1024 threads
    int lane = t & 31, w = t >> 5;
    const int CH = 20;                   // 1024*20 >= NT
    int base = t * CH;
    int local[CH];
    int sum = 0;
#pragma unroll
    for (int i = 0; i < CH; i++) {
        int idx = base + i;
        int v = (idx < NT) ? g_cnt[idx] : 0;
        local[i] = v;
        sum += v;
    }
    int inc = sum;
#pragma unroll
    for (int o = 1; o < 32; o <<= 1) {
        int v = __shfl_up_sync(0xffffffffu, inc, o);
        if (lane >= o) inc += v;
    }
    if (lane == 31) warp_base[w] = inc;
    __syncthreads();
    if (t < 32) {
        int v = warp_base[t];
        int wi = v;
#pragma unroll
        for (int o = 1; o < 32; o <<= 1) {
            int u = __shfl_up_sync(0xffffffffu, wi, o);
            if (t >= o) wi += u;
        }
        warp_base[t] = wi - v;           // exclusive warp base
    }
    __syncthreads();
    int run = warp_base[w] + inc - sum;  // exclusive thread prefix
#pragma unroll
    for (int i = 0; i < CH; i++) {
        int idx = base + i;
        if (idx < NT) { g_off[idx] = run; run += local[i]; }
    }
    if (t == 0) g_off[NT] = ET;
    for (int i = t; i < NT + 1; i += 1024) g_cnt[i] = 0;  // reset cursors
}

__global__ void fill_kernel(const int* __restrict__ ei) {
    int j = blockIdx.x * blockDim.x + threadIdx.x;
    if (j >= ET) return;
    int s, d;
    edge_sd(j, ei, s, d);
    int pos = atomicAdd(&g_cnt[d], 1);
    g_srcidx[g_off[d] + pos] = s;
}

// ---------------- layer-1 aggregation: warp per (dst, head); writes split-bf16 h ----------------
__global__ void agg1_kernel(const float* __restrict__ b1) {
    int w = (blockIdx.x * blockDim.x + threadIdx.x) >> 5;
    int lane = threadIdx.x & 31;
    if (w >= NT * HH) return;
    int d = w >> 1;
    int h = w & 1;
    int beg = g_off[d], end = g_off[d + 1];
    float adh = g_ad1[d * HH + h];

    float m = -1e30f;
    for (int j = beg + lane; j < end; j += 32) {
        int s = g_srcidx[j];
        float e = g_as1[s * HH + h] + adh;
        e = e > 0.f ? e : NEG_SLOPE * e;
        m = fmaxf(m, e);
    }
#pragma unroll
    for (int o = 16; o > 0; o >>= 1) m = fmaxf(m, __shfl_xor_sync(0xffffffffu, m, o));

    float acc[8] = {0.f, 0.f, 0.f, 0.f, 0.f, 0.f, 0.f, 0.f};
    float denom = 0.f;
    for (int j = beg; j < end; j++) {
        int s = g_srcidx[j];
        float e = g_as1[s * HH + h] + adh;
        e = e > 0.f ? e : NEG_SLOPE * e;
        float ex = __expf(e - m);
        denom += ex;
        const float* xs = g_xw1 + (size_t)s * F1 + h * HID + lane * 8;
        float4 v0 = *(const float4*)(xs);
        float4 v1 = *(const float4*)(xs + 4);
        acc[0] += ex * v0.x; acc[1] += ex * v0.y; acc[2] += ex * v0.z; acc[3] += ex * v0.w;
        acc[4] += ex * v1.x; acc[5] += ex * v1.y; acc[6] += ex * v1.z; acc[7] += ex * v1.w;
    }
    float inv = 1.f / (denom + 1e-16f);
    __nv_bfloat16* outp = g_A2 + (size_t)d * 1024 + h * HID;
#pragma unroll
    for (int k = 0; k < 8; k++) {
        int c = lane * 8 + k;
        float v = acc[k] * inv + b1[h * HID + c];
        v = 0.5f * v * (1.f + erff(v * 0.70710678118654752f));   // exact gelu
        __nv_bfloat16 hi, lo;
        split_bf16(v, hi, lo);
        outp[c] = hi;            // hi half at cols [0,512)
        outp[512 + c] = lo;      // lo half at cols [512,1024)
    }
}

// ---------------- layer-2 aggregation ----------------
__global__ void agg2_kernel(const float* __restrict__ b2, float* __restrict__ out) {
    int d = (blockIdx.x * blockDim.x + threadIdx.x) >> 5;
    int lane = threadIdx.x & 31;
    if (d >= NT) return;
    int beg = g_off[d], end = g_off[d + 1];
    float adh = g_ad2[d];

    float m = -1e30f;
    for (int j = beg + lane; j < end; j += 32) {
        int s = g_srcidx[j];
        float e = g_as2[s] + adh;
        e = e > 0.f ? e : NEG_SLOPE * e;
        m = fmaxf(m, e);
    }
#pragma unroll
    for (int o = 16; o > 0; o >>= 1) m = fmaxf(m, __shfl_xor_sync(0xffffffffu, m, o));

    float acc[8] = {0.f, 0.f, 0.f, 0.f, 0.f, 0.f, 0.f, 0.f};
    float denom = 0.f;
    for (int j = beg; j < end; j++) {
        int s = g_srcidx[j];
        float e = g_as2[s] + adh;
        e = e > 0.f ? e : NEG_SLOPE * e;
        float ex = __expf(e - m);
        denom += ex;
        const float* xs = g_xw2 + (size_t)s * FOUT + lane * 8;
        float4 v0 = *(const float4*)(xs);
        float4 v1 = *(const float4*)(xs + 4);
        acc[0] += ex * v0.x; acc[1] += ex * v0.y; acc[2] += ex * v0.z; acc[3] += ex * v0.w;
        acc[4] += ex * v1.x; acc[5] += ex * v1.y; acc[6] += ex * v1.z; acc[7] += ex * v1.w;
    }
    float inv = 1.f / (denom + 1e-16f);
    float* outp = out + (size_t)d * FOUT + lane * 8;
    float4 o0 = make_float4(acc[0] * inv + b2[lane * 8 + 0],
                            acc[1] * inv + b2[lane * 8 + 1],
                            acc[2] * inv + b2[lane * 8 + 2],
                            acc[3] * inv + b2[lane * 8 + 3]);
    float4 o1 = make_float4(acc[4] * inv + b2[lane * 8 + 4],
                            acc[5] * inv + b2[lane * 8 + 5],
                            acc[6] * inv + b2[lane * 8 + 6],
                            acc[7] * inv + b2[lane * 8 + 7]);
    *(float4*)(outp) = o0;
    *(float4*)(outp + 4) = o1;
}

// ---------------- launch ----------------
extern "C" void kernel_launch(void* const* d_in, const int* in_sizes, int n_in,
                              void* d_out, int out_size) {
    const float* x        = (const float*)d_in[0];
    const int*   ei       = (const int*)  d_in[1];
    const float* W1       = (const float*)d_in[2];
    const float* att_src1 = (const float*)d_in[3];
    const float* att_dst1 = (const float*)d_in[4];
    const float* b1       = (const float*)d_in[5];
    const float* W2       = (const float*)d_in[6];
    const float* att_src2 = (const float*)d_in[7];
    const float* att_dst2 = (const float*)d_in[8];
    const float* b2       = (const float*)d_in[9];
    float* out = (float*)d_out;

    float *p_xw1, *p_xw2;
    __nv_bfloat16 *p_A1, *p_A2, *p_Wt1, *p_Wt2;
    cudaGetSymbolAddress((void**)&p_xw1, g_xw1);
    cudaGetSymbolAddress((void**)&p_xw2, g_xw2);
    cudaGetSymbolAddress((void**)&p_A1,  g_A1);
    cudaGetSymbolAddress((void**)&p_A2,  g_A2);
    cudaGetSymbolAddress((void**)&p_Wt1, g_Wt1);
    cudaGetSymbolAddress((void**)&p_Wt2, g_Wt2);

    static cudaStream_t s2 = nullptr;
    static cudaEvent_t evFork = nullptr, evJoin = nullptr;
    if (!s2) {
        cudaStreamCreateWithFlags(&s2, cudaStreamNonBlocking);
        cudaEventCreateWithFlags(&evFork, cudaEventDisableTiming);
        cudaEventCreateWithFlags(&evJoin, cudaEventDisableTiming);
        cudaFuncSetAttribute(gemm_kernel, cudaFuncAttributeMaxDynamicSharedMemorySize, GEMM_SMEM);
    }

    // ---- fork: CSR build on s2, independent of GEMM path ----
    cudaEventRecord(evFork, 0);
    cudaStreamWaitEvent(s2, evFork, 0);
    zero_cnt_kernel<<<(NT + 256) / 256, 256, 0, s2>>>();
    count_kernel<<<(ET + 255) / 256, 256, 0, s2>>>(ei);
    scan_kernel<<<1, 1024, 0, s2>>>();
    fill_kernel<<<(ET + 255) / 256, 256, 0, s2>>>(ei);
    cudaEventRecord(evJoin, s2);

    // ---- main stream: conversions + layer-1 GEMM + alphas ----
    conv_x_kernel<<<(NT * 128 + 255) / 256, 256>>>(x);
    conv_w1_kernel<<<(512 * 512 + 255) / 256, 256>>>(W1);
    conv_w2_kernel<<<(256 * 1024 + 255) / 256, 256>>>(W2);
    {
        dim3 grid(F1 / BN, (NT + BM - 1) / BM);
        gemm_kernel<<<grid, 256, GEMM_SMEM>>>(p_A1, p_Wt1, p_xw1, NT, F1, 256);
    }
    alpha1_kernel<<<(NT * 32 + 255) / 256, 256>>>(att_src1, att_dst1);

    // ---- join CSR, then aggregate ----
    cudaStreamWaitEvent(0, evJoin, 0);
    agg1_kernel<<<(NT * HH * 32 + 255) / 256, 256>>>(b1);

    // layer-2 GEMM: xw2 = h @ W2  (M=20000, N=256, Kreal=512)
    {
        dim3 grid(FOUT / BN, (NT + BM - 1) / BM);
        gemm_kernel<<<grid, 256, GEMM_SMEM>>>(p_A2, p_Wt2, p_xw2, NT, FOUT, 512);
    }
    alpha2_kernel<<<(NT * 32 + 255) / 256, 256>>>(att_src2, att_dst2);
    agg2_kernel<<<(NT * 32 + 255) / 256, 256>>>(b2, out);
}

// round 6
// speedup vs baseline: 1.6308x; 1.0531x over previous
#include <cuda_runtime.h>
#include <cuda_bf16.h>
#include <cuda_fp16.h>
#include <math.h>
#include <stdint.h>

// ---------------- problem constants ----------------
#define BB   2
#define NN   10000
#define NT   20000           // BB*NN nodes
#define EE   160000          // edges per graph
#define EB   320000          // BB*EE batched edges
#define ET   340000          // EB + NT self loops
#define FIN  256
#define HID  256
#define HH   2
#define F1   512             // HH*HID
#define FOUT 256
#define NEG_SLOPE 0.2f

// ---------------- device scratch ----------------
__device__ float g_xw1[(size_t)NT * F1];             // x @ W1 (fp32, for alphas)
__device__ float g_xw2[(size_t)NT * FOUT];           // h @ W2 (fp32, for alphas)
__device__ __half g_xh1[(size_t)NT * F1];            // fp16 copy for agg1 gathers
__device__ __half g_xh2[(size_t)NT * FOUT];          // fp16 copy for agg2 gathers
__device__ __nv_bfloat16 g_A1[(size_t)NT * 512];     // [x_hi(256) | x_lo(256)]
__device__ __nv_bfloat16 g_A2[(size_t)NT * 1024];    // [h_hi(512) | h_lo(512)]
__device__ __nv_bfloat16 g_Wt1[(size_t)512 * 512];   // W1^T: [n=512][hi(256)|lo(256)]
__device__ __nv_bfloat16 g_Wt2[(size_t)256 * 1024];  // W2^T: [n=256][hi(512)|lo(512)]
__device__ float g_as1[NT * HH];
__device__ float g_ad1[NT * HH];
__device__ float g_as2[NT];
__device__ float g_ad2[NT];
__device__ int   g_cnt[NT + 1];
__device__ int   g_off[NT + 1];
__device__ int   g_srcidx[ET];

// ---------------- helpers ----------------
__device__ __forceinline__ uint32_t smem_u32(const void* p) {
    return (uint32_t)__cvta_generic_to_shared(p);
}
__device__ __forceinline__ void cp16(uint32_t dst, const void* src, int src_sz) {
    asm volatile("cp.async.cg.shared.global [%0], [%1], 16, %2;"
                 :: "r"(dst), "l"(src), "r"(src_sz) : "memory");
}
__device__ __forceinline__ void cp_commit() {
    asm volatile("cp.async.commit_group;" ::: "memory");
}
template <int N>
__device__ __forceinline__ void cp_wait() {
    asm volatile("cp.async.wait_group %0;" :: "n"(N) : "memory");
}
__device__ __forceinline__ void ldm4(uint32_t* r, uint32_t addr) {
    asm volatile("ldmatrix.sync.aligned.m8n8.x4.shared.b16 {%0,%1,%2,%3}, [%4];"
                 : "=r"(r[0]), "=r"(r[1]), "=r"(r[2]), "=r"(r[3]) : "r"(addr));
}
__device__ __forceinline__ void mma16816(float* c, const uint32_t* a, const uint32_t* b) {
    asm volatile(
        "mma.sync.aligned.m16n8k16.row.col.f32.bf16.bf16.f32 "
        "{%0,%1,%2,%3}, {%4,%5,%6,%7}, {%8,%9}, {%0,%1,%2,%3};"
        : "+f"(c[0]), "+f"(c[1]), "+f"(c[2]), "+f"(c[3])
        : "r"(a[0]), "r"(a[1]), "r"(a[2]), "r"(a[3]), "r"(b[0]), "r"(b[1]));
}
__device__ __forceinline__ void split_bf16(float f, __nv_bfloat16& hi, __nv_bfloat16& lo) {
    hi = __float2bfloat16(f);
    lo = __float2bfloat16(f - __bfloat162float(hi));
}
// XOR swizzle: 64B rows, chunk' = chunk ^ ((row>>1)&3); conflict-free ldmatrix, 16B-aligned
__device__ __forceinline__ uint32_t swz(int row, int cByte) {
    return (uint32_t)(row * 64 + (cByte ^ ((((row >> 1) & 3)) << 4)));
}

// ---------------- bf16x3 mma.sync GEMM, 3-stage cp.async, BKr=32 ----------------
// C = A @ Bt^T, A:[M][2K]=[Ah|Al], Bt:[N][2K]=[Bh|Bl] bf16; AhBh+AhBl+AlBh, fp32 acc.
#define BM 128
#define BN 128
#define BKr 32                       // real-k per main-loop iter
#define TILE_B (128 * 64)            // 8192 bytes per tile (no padding, swizzled)
#define STAGE_B (4 * TILE_B)         // Ah, Al, Bh, Bl = 32768
#define NSTG 3
#define GEMM_SMEM (NSTG * STAGE_B)   // 98304 bytes

__global__ __launch_bounds__(256, 2)
void gemm_kernel(const __nv_bfloat16* __restrict__ A,
                 const __nv_bfloat16* __restrict__ Bt,
                 float* __restrict__ C, __half* __restrict__ Ch,
                 int M, int N, int K) {
    extern __shared__ char sm[];
    const int tid = threadIdx.x;
    const int lane = tid & 31;
    const int wid = tid >> 5;
    const int wm = wid & 3;          // 4 warps over M (32 rows each)
    const int wn = wid >> 2;         // 2 warps over N (64 cols each)
    const int m0 = blockIdx.y * BM;
    const int n0 = blockIdx.x * BN;
    const int K2 = 2 * K;
    const uint32_t sbase = smem_u32(sm);

    float acc[2][8][4];
#pragma unroll
    for (int i = 0; i < 2; i++)
#pragma unroll
        for (int j = 0; j < 8; j++)
#pragma unroll
            for (int t = 0; t < 4; t++) acc[i][j][t] = 0.f;

    // loader: row = tid>>1 (0..127), chunk pair (tid&1): chunks {0,1} or {2,3} (16B each)
    const int lrow = tid >> 1;
    const int cb = (tid & 1) * 32;                 // base chunk byte {0,32}
    const uint32_t sw0 = swz(lrow, cb);
    const uint32_t sw1 = swz(lrow, cb + 16);
    const int ke = (tid & 1) * 16;                 // element offset within 32-elem slab
    const __nv_bfloat16* gA = A + (size_t)(m0 + lrow) * K2;
    const __nv_bfloat16* gB = Bt + (size_t)(n0 + lrow) * K2;
    const int a_ok = (m0 + lrow) < M ? 16 : 0;

    const int NIT = K / BKr;

    auto issue = [&](int it) {
        const int s = it % NSTG;
        const int k0 = it * BKr + ke;
        uint32_t d = sbase + s * STAGE_B;
        cp16(d + sw0,              gA + k0,         a_ok);
        cp16(d + sw1,              gA + k0 + 8,     a_ok);
        cp16(d + TILE_B + sw0,     gA + K + k0,     a_ok);
        cp16(d + TILE_B + sw1,     gA + K + k0 + 8, a_ok);
        cp16(d + 2 * TILE_B + sw0, gB + k0,         16);
        cp16(d + 2 * TILE_B + sw1, gB + k0 + 8,     16);
        cp16(d + 3 * TILE_B + sw0, gB + K + k0,     16);
        cp16(d + 3 * TILE_B + sw1, gB + K + k0 + 8, 16);
        cp_commit();
    };

    issue(0); issue(1);

    const int arow = wm * 32 + (lane & 15);        // + mf*16
    const int acb = (lane >> 4) * 16;              // + k16*32
    const int brow = wn * 64 + (lane & 7) + ((lane >> 4) << 3);  // + ng*16
    const int bcb = ((lane >> 3) & 1) * 16;        // + k16*32

    for (int it = 0; it < NIT; it++) {
        const int s = it % NSTG;
        cp_wait<NSTG - 2>();
        __syncthreads();
        if (it + 2 < NIT) issue(it + 2); else cp_commit();

        const uint32_t base = sbase + s * STAGE_B;
#pragma unroll
        for (int k16 = 0; k16 < 2; k16++) {
            const int kc = acb + k16 * 32;
            uint32_t ah[2][4], al[2][4];
#pragma unroll
            for (int mf = 0; mf < 2; mf++) {
                ldm4(ah[mf], base + swz(arow + mf * 16, kc));
                ldm4(al[mf], base + TILE_B + swz(arow + mf * 16, kc));
            }
            const int kb = bcb + k16 * 32;
#pragma unroll
            for (int ng = 0; ng < 4; ng++) {
                uint32_t bh[4], bl[4];
                ldm4(bh, base + 2 * TILE_B + swz(brow + ng * 16, kb));
                ldm4(bl, base + 3 * TILE_B + swz(brow + ng * 16, kb));
#pragma unroll
                for (int mf = 0; mf < 2; mf++) {
#pragma unroll
                    for (int t = 0; t < 2; t++) {
                        float* c = acc[mf][ng * 2 + t];
                        mma16816(c, ah[mf], bh + 2 * t);
                        mma16816(c, ah[mf], bl + 2 * t);
                        mma16816(c, al[mf], bh + 2 * t);
                    }
                }
            }
        }
    }

    // epilogue: fp32 C + fp16 copy Ch
#pragma unroll
    for (int mf = 0; mf < 2; mf++) {
        const int mA = m0 + wm * 32 + mf * 16 + (lane >> 2);
        const int mB = mA + 8;
#pragma unroll
        for (int nf = 0; nf < 8; nf++) {
            const int n = n0 + wn * 64 + nf * 8 + (lane & 3) * 2;
            const float* c = acc[mf][nf];
            if (mA < M) {
                *(float2*)(C + (size_t)mA * N + n) = make_float2(c[0], c[1]);
                *(__half2*)(Ch + (size_t)mA * N + n) = __floats2half2_rn(c[0], c[1]);
            }
            if (mB < M) {
                *(float2*)(C + (size_t)mB * N + n) = make_float2(c[2], c[3]);
                *(__half2*)(Ch + (size_t)mB * N + n) = __floats2half2_rn(c[2], c[3]);
            }
        }
    }
}

// ---------------- conversion kernels ----------------
__global__ void conv_x_kernel(const float* __restrict__ x) {
    int i = blockIdx.x * blockDim.x + threadIdx.x;
    if (i >= NT * 128) return;
    int row = i >> 7;
    int c2 = (i & 127) << 1;
    float2 f = *(const float2*)(x + (size_t)row * FIN + c2);
    __nv_bfloat16 h0, l0, h1, l1;
    split_bf16(f.x, h0, l0);
    split_bf16(f.y, h1, l1);
    __nv_bfloat162 hp; hp.x = h0; hp.y = h1;
    __nv_bfloat162 lp; lp.x = l0; lp.y = l1;
    *(__nv_bfloat162*)(g_A1 + (size_t)row * 512 + c2) = hp;
    *(__nv_bfloat162*)(g_A1 + (size_t)row * 512 + 256 + c2) = lp;
}

__global__ void conv_w1_kernel(const float* __restrict__ W1) {
    int i = blockIdx.x * blockDim.x + threadIdx.x;   // over 512*512
    if (i >= 512 * 512) return;
    int n = i >> 9, k = i & 511;
    int ks = k & 255;
    float f = W1[(size_t)ks * F1 + n];
    __nv_bfloat16 hi, lo;
    split_bf16(f, hi, lo);
    g_Wt1[i] = (k < 256) ? hi : lo;
}

__global__ void conv_w2_kernel(const float* __restrict__ W2) {
    int i = blockIdx.x * blockDim.x + threadIdx.x;   // over 256*1024
    if (i >= 256 * 1024) return;
    int n = i >> 10, k = i & 1023;
    int ks = k & 511;
    float f = W2[(size_t)ks * FOUT + n];
    __nv_bfloat16 hi, lo;
    split_bf16(f, hi, lo);
    g_Wt2[i] = (k < 512) ? hi : lo;
}

// ---------------- edge enumeration ----------------
__device__ __forceinline__ void edge_sd(int j, const int* ei, int& s, int& d) {
    if (j < EB) {
        int b = j / EE;
        int k = j - b * EE;
        s = ei[k]      + b * NN;
        d = ei[EE + k] + b * NN;
    } else {
        s = d = j - EB;
    }
}

// ---------------- alphas (read fp32) ----------------
__global__ void alpha1_kernel(const float* __restrict__ att_src,
                              const float* __restrict__ att_dst) {
    int gid = blockIdx.x * blockDim.x + threadIdx.x;
    int w = gid >> 5;
    int lane = gid & 31;
    if (w >= NT) return;
    const float* xw = g_xw1 + (size_t)w * F1;
#pragma unroll
    for (int h = 0; h < HH; h++) {
        float ps = 0.f, pd = 0.f;
#pragma unroll
        for (int it = 0; it < 8; it++) {
            int c = lane + it * 32;
            float v = xw[h * HID + c];
            ps += v * att_src[h * HID + c];
            pd += v * att_dst[h * HID + c];
        }
#pragma unroll
        for (int o = 16; o > 0; o >>= 1) {
            ps += __shfl_xor_sync(0xffffffffu, ps, o);
            pd += __shfl_xor_sync(0xffffffffu, pd, o);
        }
        if (lane == 0) { g_as1[w * HH + h] = ps; g_ad1[w * HH + h] = pd; }
    }
}

__global__ void alpha2_kernel(const float* __restrict__ att_src,
                              const float* __restrict__ att_dst) {
    int gid = blockIdx.x * blockDim.x + threadIdx.x;
    int w = gid >> 5;
    int lane = gid & 31;
    if (w >= NT) return;
    const float* xw = g_xw2 + (size_t)w * FOUT;
    float ps = 0.f, pd = 0.f;
#pragma unroll
    for (int it = 0; it < 8; it++) {
        int c = lane + it * 32;
        float v = xw[c];
        ps += v * att_src[c];
        pd += v * att_dst[c];
    }
#pragma unroll
    for (int o = 16; o > 0; o >>= 1) {
        ps += __shfl_xor_sync(0xffffffffu, ps, o);
        pd += __shfl_xor_sync(0xffffffffu, pd, o);
    }
    if (lane == 0) { g_as2[w] = ps; g_ad2[w] = pd; }
}

// ---------------- CSR build (forked stream) ----------------
__global__ void zero_cnt_kernel() {
    int i = blockIdx.x * blockDim.x + threadIdx.x;
    if (i <= NT) g_cnt[i] = 0;
}

__global__ void count_kernel(const int* __restrict__ ei) {
    int j = blockIdx.x * blockDim.x + threadIdx.x;
    if (j >= ET) return;
    int s, d;
    edge_sd(j, ei, s, d);
    atomicAdd(&g_cnt[d], 1);
}

__global__ void scan_kernel() {
    __shared__ int warp_base[32];
    int t = threadIdx.x;                 // 1024 threads
    int lane = t & 31, w = t >> 5;
    const int CH = 20;                   // 1024*20 >= NT
    int base = t * CH;
    int local[CH];
    int sum = 0;
#pragma unroll
    for (int i = 0; i < CH; i++) {
        int idx = base + i;
        int v = (idx < NT) ? g_cnt[idx] : 0;
        local[i] = v;
        sum += v;
    }
    int inc = sum;
#pragma unroll
    for (int o = 1; o < 32; o <<= 1) {
        int v = __shfl_up_sync(0xffffffffu, inc, o);
        if (lane >= o) inc += v;
    }
    if (lane == 31) warp_base[w] = inc;
    __syncthreads();
    if (t < 32) {
        int v = warp_base[t];
        int wi = v;
#pragma unroll
        for (int o = 1; o < 32; o <<= 1) {
            int u = __shfl_up_sync(0xffffffffu, wi, o);
            if (t >= o) wi += u;
        }
        warp_base[t] = wi - v;           // exclusive warp base
    }
    __syncthreads();
    int run = warp_base[w] + inc - sum;  // exclusive thread prefix
#pragma unroll
    for (int i = 0; i < CH; i++) {
        int idx = base + i;
        if (idx < NT) { g_off[idx] = run; run += local[i]; }
    }
    if (t == 0) g_off[NT] = ET;
    for (int i = t; i < NT + 1; i += 1024) g_cnt[i] = 0;  // reset cursors
}

__global__ void fill_kernel(const int* __restrict__ ei) {
    int j = blockIdx.x * blockDim.x + threadIdx.x;
    if (j >= ET) return;
    int s, d;
    edge_sd(j, ei, s, d);
    int pos = atomicAdd(&g_cnt[d], 1);
    g_srcidx[g_off[d] + pos] = s;
}

// ---------------- layer-1 aggregation: warp per (dst, head), fp16 gather, no max-pass ----------------
__global__ void agg1_kernel(const float* __restrict__ b1) {
    int w = (blockIdx.x * blockDim.x + threadIdx.x) >> 5;
    int lane = threadIdx.x & 31;
    if (w >= NT * HH) return;
    int d = w >> 1;
    int h = w & 1;
    int beg = g_off[d], end = g_off[d + 1];
    float adh = g_ad1[d * HH + h];

    float acc[8] = {0.f, 0.f, 0.f, 0.f, 0.f, 0.f, 0.f, 0.f};
    float denom = 0.f;
    for (int j = beg; j < end; j++) {
        int s = g_srcidx[j];
        float e = g_as1[s * HH + h] + adh;
        e = e > 0.f ? e : NEG_SLOPE * e;
        float ex = __expf(e);                 // |e| small; no max-sub needed
        denom += ex;
        const __half2* xs = (const __half2*)(g_xh1 + (size_t)s * F1 + h * HID + lane * 8);
        uint2 raw0 = *(const uint2*)(xs);
        uint2 raw1 = *(const uint2*)(xs + 2);
        float2 f0 = __half22float2(*(const __half2*)&raw0.x);
        float2 f1 = __half22float2(*(const __half2*)&raw0.y);
        float2 f2 = __half22float2(*(const __half2*)&raw1.x);
        float2 f3 = __half22float2(*(const __half2*)&raw1.y);
        acc[0] += ex * f0.x; acc[1] += ex * f0.y;
        acc[2] += ex * f1.x; acc[3] += ex * f1.y;
        acc[4] += ex * f2.x; acc[5] += ex * f2.y;
        acc[6] += ex * f3.x; acc[7] += ex * f3.y;
    }
    float inv = 1.f / (denom + 1e-16f);
    __nv_bfloat16* outp = g_A2 + (size_t)d * 1024 + h * HID;
#pragma unroll
    for (int k = 0; k < 8; k++) {
        int c = lane * 8 + k;
        float v = acc[k] * inv + b1[h * HID + c];
        v = 0.5f * v * (1.f + erff(v * 0.70710678118654752f));   // exact gelu
        __nv_bfloat16 hi, lo;
        split_bf16(v, hi, lo);
        outp[c] = hi;            // hi half at cols [0,512)
        outp[512 + c] = lo;      // lo half at cols [512,1024)
    }
}

// ---------------- layer-2 aggregation: warp per dst, fp16 gather ----------------
__global__ void agg2_kernel(const float* __restrict__ b2, float* __restrict__ out) {
    int d = (blockIdx.x * blockDim.x + threadIdx.x) >> 5;
    int lane = threadIdx.x & 31;
    if (d >= NT) return;
    int beg = g_off[d], end = g_off[d + 1];
    float adh = g_ad2[d];

    float acc[8] = {0.f, 0.f, 0.f, 0.f, 0.f, 0.f, 0.f, 0.f};
    float denom = 0.f;
    for (int j = beg; j < end; j++) {
        int s = g_srcidx[j];
        float e = g_as2[s] + adh;
        e = e > 0.f ? e : NEG_SLOPE * e;
        float ex = __expf(e);
        denom += ex;
        const __half2* xs = (const __half2*)(g_xh2 + (size_t)s * FOUT + lane * 8);
        uint2 raw0 = *(const uint2*)(xs);
        uint2 raw1 = *(const uint2*)(xs + 2);
        float2 f0 = __half22float2(*(const __half2*)&raw0.x);
        float2 f1 = __half22float2(*(const __half2*)&raw0.y);
        float2 f2 = __half22float2(*(const __half2*)&raw1.x);
        float2 f3 = __half22float2(*(const __half2*)&raw1.y);
        acc[0] += ex * f0.x; acc[1] += ex * f0.y;
        acc[2] += ex * f1.x; acc[3] += ex * f1.y;
        acc[4] += ex * f2.x; acc[5] += ex * f2.y;
        acc[6] += ex * f3.x; acc[7] += ex * f3.y;
    }
    float inv = 1.f / (denom + 1e-16f);
    float* outp = out + (size_t)d * FOUT + lane * 8;
    float4 o0 = make_float4(acc[0] * inv + b2[lane * 8 + 0],
                            acc[1] * inv + b2[lane * 8 + 1],
                            acc[2] * inv + b2[lane * 8 + 2],
                            acc[3] * inv + b2[lane * 8 + 3]);
    float4 o1 = make_float4(acc[4] * inv + b2[lane * 8 + 4],
                            acc[5] * inv + b2[lane * 8 + 5],
                            acc[6] * inv + b2[lane * 8 + 6],
                            acc[7] * inv + b2[lane * 8 + 7]);
    *(float4*)(outp) = o0;
    *(float4*)(outp + 4) = o1;
}

// ---------------- launch ----------------
extern "C" void kernel_launch(void* const* d_in, const int* in_sizes, int n_in,
                              void* d_out, int out_size) {
    const float* x        = (const float*)d_in[0];
    const int*   ei       = (const int*)  d_in[1];
    const float* W1       = (const float*)d_in[2];
    const float* att_src1 = (const float*)d_in[3];
    const float* att_dst1 = (const float*)d_in[4];
    const float* b1       = (const float*)d_in[5];
    const float* W2       = (const float*)d_in[6];
    const float* att_src2 = (const float*)d_in[7];
    const float* att_dst2 = (const float*)d_in[8];
    const float* b2       = (const float*)d_in[9];
    float* out = (float*)d_out;

    float *p_xw1, *p_xw2;
    __half *p_xh1, *p_xh2;
    __nv_bfloat16 *p_A1, *p_A2, *p_Wt1, *p_Wt2;
    cudaGetSymbolAddress((void**)&p_xw1, g_xw1);
    cudaGetSymbolAddress((void**)&p_xw2, g_xw2);
    cudaGetSymbolAddress((void**)&p_xh1, g_xh1);
    cudaGetSymbolAddress((void**)&p_xh2, g_xh2);
    cudaGetSymbolAddress((void**)&p_A1,  g_A1);
    cudaGetSymbolAddress((void**)&p_A2,  g_A2);
    cudaGetSymbolAddress((void**)&p_Wt1, g_Wt1);
    cudaGetSymbolAddress((void**)&p_Wt2, g_Wt2);

    static cudaStream_t s2 = nullptr;
    static cudaEvent_t evFork = nullptr, evJoin = nullptr;
    if (!s2) {
        cudaStreamCreateWithFlags(&s2, cudaStreamNonBlocking);
        cudaEventCreateWithFlags(&evFork, cudaEventDisableTiming);
        cudaEventCreateWithFlags(&evJoin, cudaEventDisableTiming);
        cudaFuncSetAttribute(gemm_kernel, cudaFuncAttributeMaxDynamicSharedMemorySize, GEMM_SMEM);
    }

    // ---- fork: CSR build + conv_w2 on s2 (independent of gemm1 path) ----
    cudaEventRecord(evFork, 0);
    cudaStreamWaitEvent(s2, evFork, 0);
    zero_cnt_kernel<<<(NT + 256) / 256, 256, 0, s2>>>();
    count_kernel<<<(ET + 255) / 256, 256, 0, s2>>>(ei);
    scan_kernel<<<1, 1024, 0, s2>>>();
    fill_kernel<<<(ET + 255) / 256, 256, 0, s2>>>(ei);
    conv_w2_kernel<<<(256 * 1024 + 255) / 256, 256, 0, s2>>>(W2);
    cudaEventRecord(evJoin, s2);

    // ---- main stream: conversions + layer-1 GEMM + alpha1 ----
    conv_x_kernel<<<(NT * 128 + 255) / 256, 256>>>(x);
    conv_w1_kernel<<<(512 * 512 + 255) / 256, 256>>>(W1);
    {
        dim3 grid(F1 / BN, (NT + BM - 1) / BM);
        gemm_kernel<<<grid, 256, GEMM_SMEM>>>(p_A1, p_Wt1, p_xw1, p_xh1, NT, F1, 256);
    }
    alpha1_kernel<<<(NT * 32 + 255) / 256, 256>>>(att_src1, att_dst1);

    // ---- join CSR, then aggregate ----
    cudaStreamWaitEvent(0, evJoin, 0);
    agg1_kernel<<<(NT * HH * 32 + 255) / 256, 256>>>(b1);

    // layer-2 GEMM: xw2 = h @ W2  (M=20000, N=256, Kreal=512)
    {
        dim3 grid(FOUT / BN, (NT + BM - 1) / BM);
        gemm_kernel<<<grid, 256, GEMM_SMEM>>>(p_A2, p_Wt2, p_xw2, p_xh2, NT, FOUT, 512);
    }
    alpha2_kernel<<<(NT * 32 + 255) / 256, 256>>>(att_src2, att_dst2);
    agg2_kernel<<<(NT * 32 + 255) / 256, 256>>>(b2, out);
}